// round 5
// baseline (speedup 1.0000x reference)
#include <cuda_runtime.h>

#define N_NODES 50000
#define N_EDGES 200000
#define DIM_IN 128
#define D_E 32
#define D_H 256
#define D_OUT 256
#define N_FRAG 10000
#define N_GRAPH 2000
#define BN_EPS 1e-5f

// ---------------- single scratch arena (one __device__ symbol) --------------
// element offsets (floats)
#define OFF_AGG   0               /* 50000*288 = 14,400,000 */
#define OFF_AGGE  14400000        /* 50000*32  =  1,600,000 */
#define OFF_H1    16000000        /* 50000*256 = 12,800,000 */
#define OFF_H     28800000        /* 50000*256 */
#define OFF_XA    41600000        /* 50000*256 */
#define OFF_XB    54400000        /* 50000*256 */
#define OFF_STAT  67200000        /* 256 colsum + 256 colsq */
#define OFF_CNT   67200512        /* N_FRAG + N_GRAPH = 12000 */
#define ARENA_SZ  67212512

__device__ __align__(16) float g_arena[ARENA_SZ];

__device__ __forceinline__ int clampi(int v, int hi) {
    return min(max(v, 0), hi - 1);
}

// ---------------- setup kernels ---------------------------------------------
__global__ void zero_setup_kernel() {
    int i = blockIdx.x * blockDim.x + threadIdx.x;
    const int NE = N_NODES * D_E;
    const int TOT = NE + (N_FRAG + N_GRAPH);
    if (i >= TOT) return;
    if (i < NE) g_arena[OFF_AGGE + i] = 0.f;
    else        g_arena[OFF_CNT + (i - NE)] = 0.f;
}

__global__ void zero_out_kernel(float* p, int n) {
    int i = blockIdx.x * blockDim.x + threadIdx.x;
    if (i < n) p[i] = 0.f;
}

__global__ void zero_stats_kernel() {
    g_arena[OFF_STAT + threadIdx.x] = 0.f;   // 512 threads
}

// scatter relu(edge_attr) into agg_e (layer-invariant; done once)
__global__ void scatter_edge_kernel(const float* __restrict__ ea,
                                    const int* __restrict__ dst) {
    int i = blockIdx.x * blockDim.x + threadIdx.x;
    if (i >= N_EDGES * D_E) return;
    int e = i >> 5;
    int c = i & 31;
    float v = fmaxf(ea[i], 0.f);
    int d = clampi(dst[e], N_NODES);
    atomicAdd(&g_arena[OFF_AGGE + d * D_E + c], v);
}

__global__ void count_nodes_kernel(const int* __restrict__ fb,
                                   const int* __restrict__ gb) {
    int n = blockIdx.x * blockDim.x + threadIdx.x;
    if (n >= N_NODES) return;
    atomicAdd(&g_arena[OFF_CNT + clampi(fb[n], N_FRAG)], 1.f);
    atomicAdd(&g_arena[OFF_CNT + N_FRAG + clampi(gb[n], N_GRAPH)], 1.f);
}

// agg[n,:din] = x[n] ((1+eps)*x residual, eps=0);  agg[n,din:] = agg_e[n]
// x_off < 0 -> external xext, else arena offset
__global__ void init_agg_kernel(const float* __restrict__ xext, int x_off, int din) {
    const float* x = (x_off < 0) ? xext : (g_arena + x_off);
    int fin = din + D_E;
    int i = blockIdx.x * blockDim.x + threadIdx.x;
    if (i >= N_NODES * fin) return;
    int n = i / fin;
    int c = i - n * fin;
    g_arena[OFF_AGG + i] = (c < din) ? x[(size_t)n * din + c]
                                     : g_arena[OFF_AGGE + n * D_E + (c - din)];
}

// agg[dst,:din] += relu(x[src])  (float4 gather, 4 scalar global atomics)
__global__ void scatter_x_kernel(const float* __restrict__ xext, int x_off,
                                 const int* __restrict__ src,
                                 const int* __restrict__ dst,
                                 int din) {
    const float* x = (x_off < 0) ? xext : (g_arena + x_off);
    int q4 = din >> 2;
    int total = N_EDGES * q4;
    int i = blockIdx.x * blockDim.x + threadIdx.x;
    if (i >= total) return;
    int e = i / q4;
    int q = i - e * q4;
    int s = clampi(src[e], N_NODES);
    int d = clampi(dst[e], N_NODES);
    float4 v = *(const float4*)(x + (size_t)s * din + q * 4);
    float* base = g_arena + OFF_AGG + (size_t)d * (din + D_E) + q * 4;
    atomicAdd(base + 0, fmaxf(v.x, 0.f));
    atomicAdd(base + 1, fmaxf(v.y, 0.f));
    atomicAdd(base + 2, fmaxf(v.z, 0.f));
    atomicAdd(base + 3, fmaxf(v.w, 0.f));
}

// ---------------- SGEMM: C[M,256] = relu(A[M,K] @ B[K,256] + bias) ----------
// 128x128 block tile, BK=16, 256 threads, 8x8 micro-tile.
__global__ void __launch_bounds__(256)
sgemm_bias_relu(int a_off, const float* __restrict__ Bw,
                const float* __restrict__ bias, int c_off, int M, int K) {
    const float* A = g_arena + a_off;
    float* C = g_arena + c_off;
    __shared__ float As[16][128];
    __shared__ float Bs[16][128];
    int tid = threadIdx.x;
    int row0 = blockIdx.x * 128;
    int col0 = blockIdx.y * 128;
    int tx = tid & 15, ty = tid >> 4;
    int m0 = ty * 8, n0 = tx * 8;
    float acc[8][8];
#pragma unroll
    for (int i = 0; i < 8; i++)
#pragma unroll
        for (int j = 0; j < 8; j++) acc[i][j] = 0.f;

    int nkt = K >> 4;
    for (int kt = 0; kt < nkt; kt++) {
        // A tile: 128 rows x 16 cols, stored transposed As[k][m]
#pragma unroll
        for (int l = 0; l < 2; l++) {
            int idx = l * 256 + tid;
            int ar = idx >> 2;             // 0..127
            int ac = (idx & 3) * 4;        // 0,4,8,12
            float4 v = make_float4(0.f, 0.f, 0.f, 0.f);
            int gr = row0 + ar;
            if (gr < M)
                v = *(const float4*)(A + (size_t)gr * K + kt * 16 + ac);
            As[ac + 0][ar] = v.x;
            As[ac + 1][ar] = v.y;
            As[ac + 2][ar] = v.z;
            As[ac + 3][ar] = v.w;
        }
        // B tile: 16 rows x 128 cols, row-major
#pragma unroll
        for (int l = 0; l < 2; l++) {
            int idx = l * 256 + tid;
            int br = idx >> 5;             // 0..15
            int bc = (idx & 31) * 4;       // 0..124
            float4 v = *(const float4*)(Bw + (size_t)(kt * 16 + br) * 256 + col0 + bc);
            *(float4*)(&Bs[br][bc]) = v;
        }
        __syncthreads();
#pragma unroll
        for (int k = 0; k < 16; k++) {
            float ra[8], rb[8];
#pragma unroll
            for (int i = 0; i < 8; i++) ra[i] = As[k][m0 + i];
#pragma unroll
            for (int j = 0; j < 8; j++) rb[j] = Bs[k][n0 + j];
#pragma unroll
            for (int i = 0; i < 8; i++)
#pragma unroll
                for (int j = 0; j < 8; j++) acc[i][j] += ra[i] * rb[j];
        }
        __syncthreads();
    }

    float bb[8];
#pragma unroll
    for (int j = 0; j < 8; j++) bb[j] = bias[col0 + n0 + j];
#pragma unroll
    for (int i = 0; i < 8; i++) {
        int gr = row0 + m0 + i;
        if (gr >= M) continue;
        float* crow = C + (size_t)gr * 256 + col0 + n0;
        float4 o0, o1;
        o0.x = fmaxf(acc[i][0] + bb[0], 0.f);
        o0.y = fmaxf(acc[i][1] + bb[1], 0.f);
        o0.z = fmaxf(acc[i][2] + bb[2], 0.f);
        o0.w = fmaxf(acc[i][3] + bb[3], 0.f);
        o1.x = fmaxf(acc[i][4] + bb[4], 0.f);
        o1.y = fmaxf(acc[i][5] + bb[5], 0.f);
        o1.z = fmaxf(acc[i][6] + bb[6], 0.f);
        o1.w = fmaxf(acc[i][7] + bb[7], 0.f);
        *(float4*)(crow) = o0;
        *(float4*)(crow + 4) = o1;
    }
}

// ---------------- BN stats / normalize --------------------------------------
__global__ void colstats_kernel() {
    int c = threadIdx.x;   // 256
    float s = 0.f, s2 = 0.f;
    for (int rr = blockIdx.x; rr < N_NODES; rr += gridDim.x) {
        float v = g_arena[OFF_H + (size_t)rr * 256 + c];
        s += v;
        s2 += v * v;
    }
    atomicAdd(&g_arena[OFF_STAT + c], s);
    atomicAdd(&g_arena[OFF_STAT + 256 + c], s2);
}

__global__ void bn_norm_kernel(const float* __restrict__ gamma,
                               const float* __restrict__ beta,
                               int out_off) {
    int i = blockIdx.x * blockDim.x + threadIdx.x;
    if (i >= N_NODES * 256) return;
    int c = i & 255;
    const float invN = 1.f / (float)N_NODES;
    float mu = g_arena[OFF_STAT + c] * invN;
    float var = g_arena[OFF_STAT + 256 + c] * invN - mu * mu;
    float rs = rsqrtf(var + BN_EPS);
    g_arena[out_off + i] = gamma[c] * (g_arena[OFF_H + i] - mu) * rs + beta[c];
}

// ---------------- dual sqrt-pool --------------------------------------------
__global__ void pool_kernel(const int* __restrict__ fb,
                            const int* __restrict__ gb,
                            float* __restrict__ out) {
    int i = blockIdx.x * blockDim.x + threadIdx.x;
    if (i >= N_NODES * 256) return;
    int n = i >> 8;
    int c = i & 255;
    float v = g_arena[OFF_XA + i];
    int f = clampi(fb[n], N_FRAG);
    int g2 = clampi(gb[n], N_GRAPH);
    float wf = rsqrtf(fmaxf(g_arena[OFF_CNT + f], 1.f));
    float wg = rsqrtf(fmaxf(g_arena[OFF_CNT + N_FRAG + g2], 1.f));
    atomicAdd(&out[(size_t)f * 256 + c], v * wf);
    atomicAdd(&out[(size_t)N_FRAG * 256 + (size_t)g2 * 256 + c], v * wg);
}

// ---------------- driver -----------------------------------------------------
extern "C" void kernel_launch(void* const* d_in, const int* in_sizes, int n_in,
                              void* d_out, int out_size) {
    const float* x = (const float*)d_in[0];
    const float* ea = (const float*)d_in[1];
    const int* ei = (const int*)d_in[2];     // int32! (JAX x64 disabled)
    const int* src = ei;
    const int* dst = ei + N_EDGES;
    const int* fb = (const int*)d_in[3];
    const int* gb = (const int*)d_in[4];

    const float* W1[3] = {(const float*)d_in[5], (const float*)d_in[11], (const float*)d_in[17]};
    const float* B1[3] = {(const float*)d_in[6], (const float*)d_in[12], (const float*)d_in[18]};
    const float* W2[3] = {(const float*)d_in[7], (const float*)d_in[13], (const float*)d_in[19]};
    const float* B2[3] = {(const float*)d_in[8], (const float*)d_in[14], (const float*)d_in[20]};
    const float* GG[3] = {(const float*)d_in[9], (const float*)d_in[15], (const float*)d_in[21]};
    const float* BB[3] = {(const float*)d_in[10], (const float*)d_in[16], (const float*)d_in[22]};

    float* out = (float*)d_out;
    const int T = 256;

    // one-time setup per launch
    {
        int tot = N_NODES * D_E + N_FRAG + N_GRAPH;
        zero_setup_kernel<<<(tot + T - 1) / T, T>>>();
        zero_out_kernel<<<(out_size + T - 1) / T, T>>>(out, out_size);
        scatter_edge_kernel<<<(N_EDGES * D_E + T - 1) / T, T>>>(ea, dst);
        count_nodes_kernel<<<(N_NODES + T - 1) / T, T>>>(fb, gb);
    }

    int xin_off = -1;          // layer 0 reads external x
    int xout_off = OFF_XA;     // l0 -> XA, l1 -> XB, l2 -> XA

    for (int l = 0; l < 3; l++) {
        int din = (l == 0) ? DIM_IN : D_H;
        int fin = din + D_E;

        zero_stats_kernel<<<1, 512>>>();
        init_agg_kernel<<<(N_NODES * fin + T - 1) / T, T>>>(x, xin_off, din);
        scatter_x_kernel<<<(N_EDGES * (din / 4) + T - 1) / T, T>>>(x, xin_off, src, dst, din);

        dim3 grid((N_NODES + 127) / 128, 2);
        sgemm_bias_relu<<<grid, 256>>>(OFF_AGG, W1[l], B1[l], OFF_H1, N_NODES, fin);
        sgemm_bias_relu<<<grid, 256>>>(OFF_H1, W2[l], B2[l], OFF_H, N_NODES, 256);

        colstats_kernel<<<256, 256>>>();
        bn_norm_kernel<<<(N_NODES * 256 + T - 1) / T, T>>>(GG[l], BB[l], xout_off);

        xin_off = xout_off;
        xout_off = (xout_off == OFF_XA) ? OFF_XB : OFF_XA;
    }

    // final features are in XA (l0->A, l1->B, l2->A)
    pool_kernel<<<(N_NODES * 256 + T - 1) / T, T>>>(fb, gb, out);
}

// round 8
// speedup vs baseline: 1.3964x; 1.3964x over previous
#include <cuda_runtime.h>
#include <cuda_bf16.h>
#include <cstdint>

#define N_NODES 50000
#define N_EDGES 200000
#define DIM_IN 128
#define D_E 32
#define D_H 256
#define D_OUT 256
#define N_FRAG 10000
#define N_GRAPH 2000
#define BN_EPS 1e-5f

// ---------------- single scratch arena (one __device__ symbol) --------------
#define OFF_AGG   0               /* 50000*288 */
#define OFF_AGGE  14400000        /* 50000*32  */
#define OFF_H1    16000000        /* 50000*256 */
#define OFF_H     28800000        /* 50000*256 */
#define OFF_XA    41600000
#define OFF_XB    54400000
#define OFF_STAT  67200000        /* 512 */
#define OFF_CNT   67200512        /* 12000 */
#define OFF_WT1H  67212512        /* up to 256*288 bf16 = 36864 floats each */
#define OFF_WT1L  (OFF_WT1H + 40960)
#define OFF_WT2H  (OFF_WT1L + 40960)
#define OFF_WT2L  (OFF_WT2H + 40960)
#define ARENA_SZ  (OFF_WT2L + 40960)

__device__ __align__(16) float g_arena[ARENA_SZ];

__device__ __forceinline__ int clampi(int v, int hi) {
    return min(max(v, 0), hi - 1);
}

__device__ __forceinline__ uint32_t smem_u32(const void* p) {
    uint32_t a;
    asm("{ .reg .u64 t; cvta.to.shared.u64 t, %1; cvt.u32.u64 %0, t; }" : "=r"(a) : "l"(p));
    return a;
}

// ldmatrix x4 (non-transposed), sm_80+ baseline feature
__device__ __forceinline__ void ldsm_x4(uint32_t* r, uint32_t addr) {
    asm volatile("ldmatrix.sync.aligned.m8n8.x4.shared.b16 {%0,%1,%2,%3}, [%4];"
        : "=r"(r[0]), "=r"(r[1]), "=r"(r[2]), "=r"(r[3]) : "r"(addr));
}

// bf16 mma m16n8k16, fp32 accumulate (sm_80+ baseline)
__device__ __forceinline__ void mma_bf16(float* c, const uint32_t* a, const uint32_t* b) {
    asm volatile("mma.sync.aligned.m16n8k16.row.col.f32.bf16.bf16.f32 "
        "{%0,%1,%2,%3},{%4,%5,%6,%7},{%8,%9},{%0,%1,%2,%3};"
        : "+f"(c[0]), "+f"(c[1]), "+f"(c[2]), "+f"(c[3])
        : "r"(a[0]), "r"(a[1]), "r"(a[2]), "r"(a[3]), "r"(b[0]), "r"(b[1]));
}

// ---------------- setup kernels ---------------------------------------------
__global__ void zero_setup_kernel() {
    int i = blockIdx.x * blockDim.x + threadIdx.x;
    const int NE = N_NODES * D_E;
    const int TOT = NE + (N_FRAG + N_GRAPH);
    if (i >= TOT) return;
    if (i < NE) g_arena[OFF_AGGE + i] = 0.f;
    else        g_arena[OFF_CNT + (i - NE)] = 0.f;
}

__global__ void zero_out_kernel(float* p, int n) {
    int i = blockIdx.x * blockDim.x + threadIdx.x;
    if (i < n) p[i] = 0.f;
}

__global__ void zero_stats_kernel() {
    g_arena[OFF_STAT + threadIdx.x] = 0.f;   // 512 threads
}

__global__ void scatter_edge_kernel(const float* __restrict__ ea,
                                    const int* __restrict__ dst) {
    int i = blockIdx.x * blockDim.x + threadIdx.x;
    if (i >= N_EDGES * D_E) return;
    int e = i >> 5;
    int c = i & 31;
    float v = fmaxf(ea[i], 0.f);
    int d = clampi(dst[e], N_NODES);
    atomicAdd(&g_arena[OFF_AGGE + d * D_E + c], v);
}

__global__ void count_nodes_kernel(const int* __restrict__ fb,
                                   const int* __restrict__ gb) {
    int n = blockIdx.x * blockDim.x + threadIdx.x;
    if (n >= N_NODES) return;
    atomicAdd(&g_arena[OFF_CNT + clampi(fb[n], N_FRAG)], 1.f);
    atomicAdd(&g_arena[OFF_CNT + N_FRAG + clampi(gb[n], N_GRAPH)], 1.f);
}

// agg[n,:din] = x[n];  agg[n,din:] = agg_e[n]
__global__ void init_agg_kernel(const float* __restrict__ xext, int x_off, int din) {
    const float* x = (x_off < 0) ? xext : (g_arena + x_off);
    int fin = din + D_E;
    int i = blockIdx.x * blockDim.x + threadIdx.x;
    if (i >= N_NODES * fin) return;
    int n = i / fin;
    int c = i - n * fin;
    g_arena[OFF_AGG + i] = (c < din) ? x[(size_t)n * din + c]
                                     : g_arena[OFF_AGGE + n * D_E + (c - din)];
}

// agg[dst,:din] += relu(x[src])
__global__ void scatter_x_kernel(const float* __restrict__ xext, int x_off,
                                 const int* __restrict__ src,
                                 const int* __restrict__ dst,
                                 int din) {
    const float* x = (x_off < 0) ? xext : (g_arena + x_off);
    int q4 = din >> 2;
    int total = N_EDGES * q4;
    int i = blockIdx.x * blockDim.x + threadIdx.x;
    if (i >= total) return;
    int e = i / q4;
    int q = i - e * q4;
    int s = clampi(src[e], N_NODES);
    int d = clampi(dst[e], N_NODES);
    float4 v = *(const float4*)(x + (size_t)s * din + q * 4);
    float* base = g_arena + OFF_AGG + (size_t)d * (din + D_E) + q * 4;
    atomicAdd(base + 0, fmaxf(v.x, 0.f));
    atomicAdd(base + 1, fmaxf(v.y, 0.f));
    atomicAdd(base + 2, fmaxf(v.z, 0.f));
    atomicAdd(base + 3, fmaxf(v.w, 0.f));
}

// ---------------- weight transpose + bf16 hi/lo split ------------------------
// W [K,256] fp32 -> Wt_hi/Wt_lo [256, K] bf16  (K % 32 == 0, no padding)
__global__ void convert_w_kernel(const float* __restrict__ W, int K,
                                 int hi_off, int lo_off) {
    __nv_bfloat16* H = (__nv_bfloat16*)(g_arena + hi_off);
    __nv_bfloat16* L = (__nv_bfloat16*)(g_arena + lo_off);
    int i = blockIdx.x * blockDim.x + threadIdx.x;
    if (i >= 256 * K) return;
    int n = i / K;
    int k = i - n * K;
    float w = W[(size_t)k * 256 + n];
    __nv_bfloat16 h = __float2bfloat16(w);
    float lo = w - __bfloat162float(h);
    H[i] = h;
    L[i] = __float2bfloat16(lo);
}

// ---------------- HMMA GEMM: C[M,256] = relu(A[M,K] @ W[K,256] + bias) ------
// bf16x3: Ahi*Bhi + Ahi*Blo + Alo*Bhi, fp32 accum.
// BM=128 BN=128 BK=32, 256 threads (8 warps 4x2), warp tile 32x64.
__global__ void __launch_bounds__(256)
mma_gemm(int a_off, int c_off, int M, int K,
         int wth_off, int wtl_off, const float* __restrict__ bias) {
    __shared__ __align__(16) __nv_bfloat16 sAh[128][40];
    __shared__ __align__(16) __nv_bfloat16 sAl[128][40];
    __shared__ __align__(16) __nv_bfloat16 sBh[128][40];
    __shared__ __align__(16) __nv_bfloat16 sBl[128][40];

    const float* A = g_arena + a_off;
    float* C = g_arena + c_off;
    const __nv_bfloat16* WH = (const __nv_bfloat16*)(g_arena + wth_off);
    const __nv_bfloat16* WL = (const __nv_bfloat16*)(g_arena + wtl_off);

    int tid = threadIdx.x, lane = tid & 31, wid = tid >> 5;
    int wy = wid >> 1, wx = wid & 1;                 // 4 x 2 warp grid
    int row0 = blockIdx.x * 128, col0 = blockIdx.y * 128;

    float acc[2][8][4];
#pragma unroll
    for (int mt = 0; mt < 2; mt++)
#pragma unroll
        for (int nt = 0; nt < 8; nt++)
#pragma unroll
            for (int r = 0; r < 4; r++) acc[mt][nt][r] = 0.f;

    // loader mapping: thread t -> row t/2, col half (t&1)*16
    int ar = tid >> 1;
    int ac = (tid & 1) * 16;
    int gr = min(row0 + ar, M - 1);
    const float* ap = A + (size_t)gr * K + ac;
    const __nv_bfloat16* bph = WH + (size_t)(col0 + ar) * K + ac;
    const __nv_bfloat16* bpl = WL + (size_t)(col0 + ar) * K + ac;

    for (int k0 = 0; k0 < K; k0 += 32) {
        // A tile: fp32 -> hi/lo bf16
#pragma unroll
        for (int q = 0; q < 4; q++) {
            float4 v = *(const float4*)(ap + k0 + q * 4);
            __nv_bfloat16 h0 = __float2bfloat16(v.x);
            __nv_bfloat16 h1 = __float2bfloat16(v.y);
            __nv_bfloat16 h2 = __float2bfloat16(v.z);
            __nv_bfloat16 h3 = __float2bfloat16(v.w);
            *(__nv_bfloat162*)&sAh[ar][ac + q * 4]     = __nv_bfloat162(h0, h1);
            *(__nv_bfloat162*)&sAh[ar][ac + q * 4 + 2] = __nv_bfloat162(h2, h3);
            *(__nv_bfloat162*)&sAl[ar][ac + q * 4] = __nv_bfloat162(
                __float2bfloat16(v.x - __bfloat162float(h0)),
                __float2bfloat16(v.y - __bfloat162float(h1)));
            *(__nv_bfloat162*)&sAl[ar][ac + q * 4 + 2] = __nv_bfloat162(
                __float2bfloat16(v.z - __bfloat162float(h2)),
                __float2bfloat16(v.w - __bfloat162float(h3)));
        }
        // B tiles (already bf16, pre-transposed [256,K])
        *(uint4*)&sBh[ar][ac]     = *(const uint4*)(bph + k0);
        *(uint4*)&sBh[ar][ac + 8] = *(const uint4*)(bph + k0 + 8);
        *(uint4*)&sBl[ar][ac]     = *(const uint4*)(bpl + k0);
        *(uint4*)&sBl[ar][ac + 8] = *(const uint4*)(bpl + k0 + 8);
        __syncthreads();

#pragma unroll
        for (int ks = 0; ks < 2; ks++) {
            int kk = ks * 16;
            uint32_t ah[2][4], al[2][4];
#pragma unroll
            for (int mt = 0; mt < 2; mt++) {
                int r = wy * 32 + mt * 16 + (lane & 15);
                int c = kk + ((lane >> 4) << 3);
                ldsm_x4(ah[mt], smem_u32(&sAh[r][c]));
                ldsm_x4(al[mt], smem_u32(&sAl[r][c]));
            }
#pragma unroll
            for (int bt = 0; bt < 4; bt++) {
                int rB = wx * 64 + bt * 16 + (lane & 7) + ((lane >> 4) << 3);
                int cB = kk + (((lane >> 3) & 1) << 3);
                uint32_t bh[4], bl[4];
                ldsm_x4(bh, smem_u32(&sBh[rB][cB]));
                ldsm_x4(bl, smem_u32(&sBl[rB][cB]));
#pragma unroll
                for (int h = 0; h < 2; h++) {
                    int nt = bt * 2 + h;
#pragma unroll
                    for (int mt = 0; mt < 2; mt++) {
                        mma_bf16(acc[mt][nt], ah[mt], bh + h * 2);
                        mma_bf16(acc[mt][nt], ah[mt], bl + h * 2);
                        mma_bf16(acc[mt][nt], al[mt], bh + h * 2);
                    }
                }
            }
        }
        __syncthreads();
    }

    // epilogue: bias + relu, fp32 stores
#pragma unroll
    for (int mt = 0; mt < 2; mt++) {
#pragma unroll
        for (int nt = 0; nt < 8; nt++) {
            int cb = col0 + wx * 64 + nt * 8 + 2 * (lane & 3);
            float b0 = bias[cb], b1 = bias[cb + 1];
#pragma unroll
            for (int hf = 0; hf < 2; hf++) {
                int r = row0 + wy * 32 + mt * 16 + (lane >> 2) + hf * 8;
                if (r < M) {
                    float2 o;
                    o.x = fmaxf(acc[mt][nt][hf * 2 + 0] + b0, 0.f);
                    o.y = fmaxf(acc[mt][nt][hf * 2 + 1] + b1, 0.f);
                    *(float2*)(C + (size_t)r * 256 + cb) = o;
                }
            }
        }
    }
}

// ---------------- BN stats / normalize --------------------------------------
__global__ void colstats_kernel() {
    int c = threadIdx.x;   // 256
    float s = 0.f, s2 = 0.f;
    for (int rr = blockIdx.x; rr < N_NODES; rr += gridDim.x) {
        float v = g_arena[OFF_H + (size_t)rr * 256 + c];
        s += v;
        s2 += v * v;
    }
    atomicAdd(&g_arena[OFF_STAT + c], s);
    atomicAdd(&g_arena[OFF_STAT + 256 + c], s2);
}

__global__ void bn_norm_kernel(const float* __restrict__ gamma,
                               const float* __restrict__ beta,
                               int out_off) {
    int i = blockIdx.x * blockDim.x + threadIdx.x;
    if (i >= N_NODES * 256) return;
    int c = i & 255;
    const float invN = 1.f / (float)N_NODES;
    float mu = g_arena[OFF_STAT + c] * invN;
    float var = g_arena[OFF_STAT + 256 + c] * invN - mu * mu;
    float rs = rsqrtf(var + BN_EPS);
    g_arena[out_off + i] = gamma[c] * (g_arena[OFF_H + i] - mu) * rs + beta[c];
}

// ---------------- dual sqrt-pool --------------------------------------------
__global__ void pool_kernel(const int* __restrict__ fb,
                            const int* __restrict__ gb,
                            float* __restrict__ out) {
    int i = blockIdx.x * blockDim.x + threadIdx.x;
    if (i >= N_NODES * 256) return;
    int n = i >> 8;
    int c = i & 255;
    float v = g_arena[OFF_XA + i];
    int f = clampi(fb[n], N_FRAG);
    int g2 = clampi(gb[n], N_GRAPH);
    float wf = rsqrtf(fmaxf(g_arena[OFF_CNT + f], 1.f));
    float wg = rsqrtf(fmaxf(g_arena[OFF_CNT + N_FRAG + g2], 1.f));
    atomicAdd(&out[(size_t)f * 256 + c], v * wf);
    atomicAdd(&out[(size_t)N_FRAG * 256 + (size_t)g2 * 256 + c], v * wg);
}

// ---------------- driver -----------------------------------------------------
extern "C" void kernel_launch(void* const* d_in, const int* in_sizes, int n_in,
                              void* d_out, int out_size) {
    const float* x = (const float*)d_in[0];
    const float* ea = (const float*)d_in[1];
    const int* ei = (const int*)d_in[2];     // int32 (JAX x64 disabled)
    const int* src = ei;
    const int* dst = ei + N_EDGES;
    const int* fb = (const int*)d_in[3];
    const int* gb = (const int*)d_in[4];

    const float* W1[3] = {(const float*)d_in[5], (const float*)d_in[11], (const float*)d_in[17]};
    const float* B1[3] = {(const float*)d_in[6], (const float*)d_in[12], (const float*)d_in[18]};
    const float* W2[3] = {(const float*)d_in[7], (const float*)d_in[13], (const float*)d_in[19]};
    const float* B2[3] = {(const float*)d_in[8], (const float*)d_in[14], (const float*)d_in[20]};
    const float* GG[3] = {(const float*)d_in[9], (const float*)d_in[15], (const float*)d_in[21]};
    const float* BB[3] = {(const float*)d_in[10], (const float*)d_in[16], (const float*)d_in[22]};

    float* out = (float*)d_out;
    const int T = 256;

    // one-time setup per launch
    {
        int tot = N_NODES * D_E + N_FRAG + N_GRAPH;
        zero_setup_kernel<<<(tot + T - 1) / T, T>>>();
        zero_out_kernel<<<(out_size + T - 1) / T, T>>>(out, out_size);
        scatter_edge_kernel<<<(N_EDGES * D_E + T - 1) / T, T>>>(ea, dst);
        count_nodes_kernel<<<(N_NODES + T - 1) / T, T>>>(fb, gb);
    }

    int xin_off = -1;          // layer 0 reads external x
    int xout_off = OFF_XA;     // l0 -> XA, l1 -> XB, l2 -> XA
    dim3 ggrid((N_NODES + 127) / 128, 2);

    for (int l = 0; l < 3; l++) {
        int din = (l == 0) ? DIM_IN : D_H;
        int fin = din + D_E;              // 160, 288, 288 — all % 32 == 0

        zero_stats_kernel<<<1, 512>>>();
        init_agg_kernel<<<(N_NODES * fin + T - 1) / T, T>>>(x, xin_off, din);
        scatter_x_kernel<<<(N_EDGES * (din / 4) + T - 1) / T, T>>>(x, xin_off, src, dst, din);

        convert_w_kernel<<<(256 * fin + T - 1) / T, T>>>(W1[l], fin, OFF_WT1H, OFF_WT1L);
        convert_w_kernel<<<(256 * 256 + T - 1) / T, T>>>(W2[l], 256, OFF_WT2H, OFF_WT2L);

        mma_gemm<<<ggrid, 256>>>(OFF_AGG, OFF_H1, N_NODES, fin, OFF_WT1H, OFF_WT1L, B1[l]);
        mma_gemm<<<ggrid, 256>>>(OFF_H1, OFF_H, N_NODES, 256, OFF_WT2H, OFF_WT2L, B2[l]);

        colstats_kernel<<<256, 256>>>();
        bn_norm_kernel<<<(N_NODES * 256 + T - 1) / T, T>>>(GG[l], BB[l], xout_off);

        xin_off = xout_off;
        xout_off = (xout_off == OFF_XA) ? OFF_XB : OFF_XA;
    }

    // final features in XA (l0->A, l1->B, l2->A)
    pool_kernel<<<(N_NODES * 256 + T - 1) / T, T>>>(fb, gb, out);
}

// round 12
// speedup vs baseline: 1.6556x; 1.1856x over previous
#include <cuda_runtime.h>
#include <cuda_bf16.h>
#include <cstdint>

#define N_NODES 50000
#define N_EDGES 200000
#define DIM_IN 128
#define D_E 32
#define D_H 256
#define N_FRAG 10000
#define N_GRAPH 2000
#define BN_EPS 1e-5f

// ---------------- float arena ------------------------------------------------
#define OFF_AGGH 0            /* bf16 [N,288] hi  -> 7.2M floats */
#define OFF_AGGL 7200000
#define OFF_H1H  14400000     /* bf16 [N,256] hi  -> 6.4M */
#define OFF_H1L  20800000
#define OFF_H    27200000     /* fp32 [N,256] */
#define OFF_XA   40000000
#define OFF_XB   52800000
#define OFF_AEH  65600000     /* bf16 [N,32] hi -> 0.8M */
#define OFF_AEL  66400000
#define OFF_STAT 67200000     /* 512 */
#define OFF_W    67200512
#define W1SZ 36864            /* floats: 288*256 bf16 max */
#define W2SZ 32768
#define WSTRIDE (2*W1SZ + 2*W2SZ)
#define ARENA_SZ (OFF_W + 3*WSTRIDE)

__device__ __align__(16) float g_arena[ARENA_SZ];

// CSR / segment scratch (ints)
__device__ int g_deg[N_NODES];
__device__ int g_cursor[N_NODES];
__device__ int g_rp[N_NODES + 1];
__device__ int g_btot[256];
__device__ int g_boff[256];
__device__ int g_elsrc[N_EDGES];
__device__ int g_eleid[N_EDGES];
__device__ int g_fstart[N_FRAG + 1];
__device__ int g_gstart[N_GRAPH + 1];

__device__ __forceinline__ int clampi(int v, int hi) {
    return min(max(v, 0), hi - 1);
}
__device__ __forceinline__ uint32_t smem_u32(const void* p) {
    uint32_t a;
    asm("{ .reg .u64 t; cvta.to.shared.u64 t, %1; cvt.u32.u64 %0, t; }" : "=r"(a) : "l"(p));
    return a;
}
__device__ __forceinline__ void ldsm_x4(uint32_t* r, uint32_t addr) {
    asm volatile("ldmatrix.sync.aligned.m8n8.x4.shared.b16 {%0,%1,%2,%3}, [%4];"
        : "=r"(r[0]), "=r"(r[1]), "=r"(r[2]), "=r"(r[3]) : "r"(addr));
}
__device__ __forceinline__ void mma_bf16(float* c, const uint32_t* a, const uint32_t* b) {
    asm volatile("mma.sync.aligned.m16n8k16.row.col.f32.bf16.bf16.f32 "
        "{%0,%1,%2,%3},{%4,%5,%6,%7},{%8,%9},{%0,%1,%2,%3};"
        : "+f"(c[0]), "+f"(c[1]), "+f"(c[2]), "+f"(c[3])
        : "r"(a[0]), "r"(a[1]), "r"(a[2]), "r"(a[3]), "r"(b[0]), "r"(b[1]));
}
__device__ __forceinline__ void cpa16(uint32_t sdst, const void* gsrc) {
    asm volatile("cp.async.ca.shared.global [%0], [%1], 16;" :: "r"(sdst), "l"(gsrc));
}
#define CP_COMMIT() asm volatile("cp.async.commit_group;" ::: "memory")
#define CP_WAIT(n)  asm volatile("cp.async.wait_group %0;" :: "n"(n) : "memory")

// ---------------- CSR build --------------------------------------------------
__global__ void csr_zero() {
    int i = blockIdx.x * blockDim.x + threadIdx.x;
    if (i < N_NODES) { g_deg[i] = 0; g_cursor[i] = 0; }
}
__global__ void csr_hist(const int* __restrict__ dst) {
    int e = blockIdx.x * blockDim.x + threadIdx.x;
    if (e >= N_EDGES) return;
    atomicAdd(&g_deg[clampi(dst[e], N_NODES)], 1);
}
__global__ void scan_local() {          // grid 196, block 256
    __shared__ int sm[256];
    int b = blockIdx.x, t = threadIdx.x;
    int n = b * 256 + t;
    int v = (n < N_NODES) ? g_deg[n] : 0;
    sm[t] = v; __syncthreads();
    for (int o = 1; o < 256; o <<= 1) {
        int x = (t >= o) ? sm[t - o] : 0; __syncthreads();
        sm[t] += x; __syncthreads();
    }
    if (n < N_NODES) g_rp[n + 1] = sm[t];
    if (t == 255) g_btot[b] = sm[255];
}
__global__ void scan_btot() {           // 1 block 256
    __shared__ int sm[256];
    int t = threadIdx.x;
    const int nb = (N_NODES + 255) / 256;
    int v = (t < nb) ? g_btot[t] : 0;
    sm[t] = v; __syncthreads();
    for (int o = 1; o < 256; o <<= 1) {
        int x = (t >= o) ? sm[t - o] : 0; __syncthreads();
        sm[t] += x; __syncthreads();
    }
    if (t < nb) g_boff[t] = sm[t] - v;  // exclusive
}
__global__ void scan_add() {
    int n = blockIdx.x * blockDim.x + threadIdx.x;
    if (n == 0) g_rp[0] = 0;
    if (n < N_NODES) g_rp[n + 1] += g_boff[n >> 8];
}
__global__ void csr_fill(const int* __restrict__ src, const int* __restrict__ dst) {
    int e = blockIdx.x * blockDim.x + threadIdx.x;
    if (e >= N_EDGES) return;
    int d = clampi(dst[e], N_NODES);
    int pos = atomicAdd(&g_cursor[d], 1);
    int idx = g_rp[d] + pos;
    if (idx < N_EDGES) {
        g_elsrc[idx] = clampi(src[e], N_NODES);
        g_eleid[idx] = e;
    }
}
// sum relu(edge_attr) per node -> hi/lo bf16 planes (layer-invariant)
__global__ void agge_split(const float* __restrict__ ea) {
    int n = blockIdx.x;
    int c = threadIdx.x;                // 32
    int s0 = g_rp[n], s1 = g_rp[n + 1];
    float v = 0.f;
    for (int j = s0; j < s1; j++)
        v += fmaxf(ea[(size_t)g_eleid[j] * D_E + c], 0.f);
    __nv_bfloat16 h = __float2bfloat16(v);
    ((__nv_bfloat16*)(g_arena + OFF_AEH))[n * D_E + c] = h;
    ((__nv_bfloat16*)(g_arena + OFF_AEL))[n * D_E + c] =
        __float2bfloat16(v - __bfloat162float(h));
}
// segment boundaries for sorted batch vectors
__global__ void seg_bounds(const int* __restrict__ fb, const int* __restrict__ gb) {
    int n = blockIdx.x * blockDim.x + threadIdx.x;
    if (n >= N_NODES) return;
    int f = clampi(fb[n], N_FRAG), g = clampi(gb[n], N_GRAPH);
    if (n == 0) {
        for (int i = 0; i <= f; i++) g_fstart[i] = 0;
        for (int i = 0; i <= g; i++) g_gstart[i] = 0;
    } else {
        int fp = clampi(fb[n - 1], N_FRAG), gp = clampi(gb[n - 1], N_GRAPH);
        for (int i = fp + 1; i <= f; i++) g_fstart[i] = n;
        for (int i = gp + 1; i <= g; i++) g_gstart[i] = n;
    }
    if (n == N_NODES - 1) {
        for (int i = f + 1; i <= N_FRAG; i++) g_fstart[i] = N_NODES;
        for (int i = g + 1; i <= N_GRAPH; i++) g_gstart[i] = N_NODES;
    }
}

// ---------------- weight transpose + split -----------------------------------
__global__ void convert_w(const float* __restrict__ W, int K, int hi_off, int lo_off) {
    __nv_bfloat16* H = (__nv_bfloat16*)(g_arena + hi_off);
    __nv_bfloat16* L = (__nv_bfloat16*)(g_arena + lo_off);
    int i = blockIdx.x * blockDim.x + threadIdx.x;
    if (i >= 256 * K) return;
    int n = i / K, k = i - n * K;
    float w = W[(size_t)k * 256 + n];
    __nv_bfloat16 h = __float2bfloat16(w);
    H[i] = h;
    L[i] = __float2bfloat16(w - __bfloat162float(h));
}

// ---------------- gather + residual + split ----------------------------------
// agg[n,c] = x[n,c] + sum_j relu(x[elsrc[j],c])  (c<din);  agg[n,din:] = aggE
// written directly as hi/lo bf16 planes, pitch fin. blockDim = fin.
__global__ void gather_split(const float* __restrict__ xext, int x_off, int din) {
    const float* x = (x_off < 0) ? xext : (g_arena + x_off);
    int n = blockIdx.x;
    int fin = din + D_E;
    __nv_bfloat16* AH = (__nv_bfloat16*)(g_arena + OFF_AGGH);
    __nv_bfloat16* AL = (__nv_bfloat16*)(g_arena + OFF_AGGL);
    int c = threadIdx.x;
    if (c >= fin) return;
    if (c >= din) {
        int ce = c - din;
        AH[(size_t)n * fin + c] = ((__nv_bfloat16*)(g_arena + OFF_AEH))[n * D_E + ce];
        AL[(size_t)n * fin + c] = ((__nv_bfloat16*)(g_arena + OFF_AEL))[n * D_E + ce];
        return;
    }
    int s0 = g_rp[n], s1 = g_rp[n + 1];
    float v = x[(size_t)n * din + c];         // residual (no relu)
    for (int j = s0; j < s1; j++)
        v += fmaxf(x[(size_t)g_elsrc[j] * din + c], 0.f);
    __nv_bfloat16 h = __float2bfloat16(v);
    AH[(size_t)n * fin + c] = h;
    AL[(size_t)n * fin + c] = __float2bfloat16(v - __bfloat162float(h));
}

// ---------------- HMMA GEMM (bf16x3, cp.async double-buffered) ---------------
// C[M,256] = relu(A @ W + bias). A,W given as hi/lo bf16 planes [rows, K].
// BM=128 BN=128 BK=16. 256 thr, 8 warps (4x2), warp tile 32x64.
// mode 0: fp32 out at o1. mode 1: bf16 hi/lo planes at o1/o2 (pitch 256).
#define GPLANE 6144            /* 128 rows * 48B */
#define GSTAGE 24576
__global__ void __launch_bounds__(256)
mma_gemm(int ah_off, int al_off, int bh_off, int bl_off,
         const float* __restrict__ bias, int M, int K,
         int mode, int o1_off, int o2_off) {
    __shared__ __align__(16) char smem[2 * GSTAGE];
    const __nv_bfloat16* AH = (const __nv_bfloat16*)(g_arena + ah_off);
    const __nv_bfloat16* AL = (const __nv_bfloat16*)(g_arena + al_off);
    const __nv_bfloat16* BH = (const __nv_bfloat16*)(g_arena + bh_off);
    const __nv_bfloat16* BL = (const __nv_bfloat16*)(g_arena + bl_off);

    int tid = threadIdx.x, lane = tid & 31, wid = tid >> 5;
    int wy = wid >> 1, wx = wid & 1;
    int row0 = blockIdx.x * 128, col0 = blockIdx.y * 128;
    uint32_t sb = smem_u32(smem);

    // loader: thread -> (row, 16B segment)
    int lrow = tid >> 1, lseg = tid & 1;
    int agr = min(row0 + lrow, M - 1);
    const __nv_bfloat16* pAH = AH + (size_t)agr * K + lseg * 8;
    const __nv_bfloat16* pAL = AL + (size_t)agr * K + lseg * 8;
    const __nv_bfloat16* pBH = BH + (size_t)(col0 + lrow) * K + lseg * 8;
    const __nv_bfloat16* pBL = BL + (size_t)(col0 + lrow) * K + lseg * 8;
    uint32_t sdst = (uint32_t)(lrow * 48 + lseg * 16);

    float acc[2][8][4];
#pragma unroll
    for (int mt = 0; mt < 2; mt++)
#pragma unroll
        for (int nt = 0; nt < 8; nt++)
#pragma unroll
            for (int r = 0; r < 4; r++) acc[mt][nt][r] = 0.f;

    int nch = K >> 4;
    // prefetch chunk 0
    {
        uint32_t b = sb + sdst;
        cpa16(b, pAH); cpa16(b + GPLANE, pAL);
        cpa16(b + 2 * GPLANE, pBH); cpa16(b + 3 * GPLANE, pBL);
        CP_COMMIT();
    }
    for (int c = 0; c < nch; c++) {
        int s = c & 1;
        if (c + 1 < nch) {
            int k0 = (c + 1) * 16;
            uint32_t b = sb + (s ^ 1) * GSTAGE + sdst;
            cpa16(b, pAH + k0); cpa16(b + GPLANE, pAL + k0);
            cpa16(b + 2 * GPLANE, pBH + k0); cpa16(b + 3 * GPLANE, pBL + k0);
            CP_COMMIT();
            CP_WAIT(1);
        } else {
            CP_WAIT(0);
        }
        __syncthreads();

        uint32_t base = sb + s * GSTAGE;
        uint32_t ah[2][4], al[2][4];
#pragma unroll
        for (int mt = 0; mt < 2; mt++) {
            int r = wy * 32 + mt * 16 + (lane & 15);
            int cc = (lane >> 4) << 3;
            ldsm_x4(ah[mt], base + r * 48 + cc * 2);
            ldsm_x4(al[mt], base + GPLANE + r * 48 + cc * 2);
        }
#pragma unroll
        for (int bt = 0; bt < 4; bt++) {
            int rB = wx * 64 + bt * 16 + (lane & 7) + ((lane >> 4) << 3);
            int cB = ((lane >> 3) & 1) << 3;
            uint32_t bh[4], bl[4];
            ldsm_x4(bh, base + 2 * GPLANE + rB * 48 + cB * 2);
            ldsm_x4(bl, base + 3 * GPLANE + rB * 48 + cB * 2);
#pragma unroll
            for (int h = 0; h < 2; h++) {
                int nt = bt * 2 + h;
#pragma unroll
                for (int mt = 0; mt < 2; mt++) {
                    mma_bf16(acc[mt][nt], ah[mt], bh + h * 2);
                    mma_bf16(acc[mt][nt], ah[mt], bl + h * 2);
                    mma_bf16(acc[mt][nt], al[mt], bh + h * 2);
                }
            }
        }
        __syncthreads();
    }

    // epilogue
#pragma unroll
    for (int mt = 0; mt < 2; mt++) {
#pragma unroll
        for (int nt = 0; nt < 8; nt++) {
            int col = col0 + wx * 64 + nt * 8 + 2 * (lane & 3);
            float b0 = bias[col], b1 = bias[col + 1];
#pragma unroll
            for (int hf = 0; hf < 2; hf++) {
                int r = row0 + wy * 32 + mt * 16 + (lane >> 2) + hf * 8;
                if (r >= M) continue;
                float v0 = fmaxf(acc[mt][nt][hf * 2 + 0] + b0, 0.f);
                float v1 = fmaxf(acc[mt][nt][hf * 2 + 1] + b1, 0.f);
                if (mode == 0) {
                    float* C = g_arena + o1_off;
                    *(float2*)(C + (size_t)r * 256 + col) = make_float2(v0, v1);
                } else {
                    __nv_bfloat16 h0 = __float2bfloat16(v0);
                    __nv_bfloat16 h1 = __float2bfloat16(v1);
                    __nv_bfloat162 hp(h0, h1);
                    __nv_bfloat162 lp(__float2bfloat16(v0 - __bfloat162float(h0)),
                                      __float2bfloat16(v1 - __bfloat162float(h1)));
                    *(__nv_bfloat162*)((__nv_bfloat16*)(g_arena + o1_off) + (size_t)r * 256 + col) = hp;
                    *(__nv_bfloat162*)((__nv_bfloat16*)(g_arena + o2_off) + (size_t)r * 256 + col) = lp;
                }
            }
        }
    }
}

// ---------------- BN ---------------------------------------------------------
__global__ void zero_stats_kernel() { g_arena[OFF_STAT + threadIdx.x] = 0.f; }

__global__ void colstats_kernel() {
    int c = threadIdx.x;
    float s = 0.f, s2 = 0.f;
    for (int rr = blockIdx.x; rr < N_NODES; rr += gridDim.x) {
        float v = g_arena[OFF_H + (size_t)rr * 256 + c];
        s += v; s2 += v * v;
    }
    atomicAdd(&g_arena[OFF_STAT + c], s);
    atomicAdd(&g_arena[OFF_STAT + 256 + c], s2);
}

__global__ void bn_norm_kernel(const float* __restrict__ gamma,
                               const float* __restrict__ beta,
                               int out_off) {
    int i = blockIdx.x * blockDim.x + threadIdx.x;
    if (i >= N_NODES * 256) return;
    int c = i & 255;
    const float invN = 1.f / (float)N_NODES;
    float mu = g_arena[OFF_STAT + c] * invN;
    float var = g_arena[OFF_STAT + 256 + c] * invN - mu * mu;
    float rs = rsqrtf(var + BN_EPS);
    g_arena[out_off + i] = gamma[c] * (g_arena[OFF_H + i] - mu) * rs + beta[c];
}

// ---------------- segment pooling (no atomics) -------------------------------
__global__ void pool_seg(int use_graph, float* __restrict__ out) {
    int f = blockIdx.x;
    const int* st = use_graph ? g_gstart : g_fstart;
    int s = min(max(st[f], 0), N_NODES);
    int e = min(max(st[f + 1], s), N_NODES);
    float w = rsqrtf(fmaxf((float)(e - s), 1.f));
    int c = threadIdx.x;   // 256
    float acc = 0.f;
    for (int r = s; r < e; r++) acc += g_arena[OFF_XA + (size_t)r * 256 + c];
    out[(size_t)f * 256 + c] = acc * w;
}

// ---------------- driver -----------------------------------------------------
extern "C" void kernel_launch(void* const* d_in, const int* in_sizes, int n_in,
                              void* d_out, int out_size) {
    const float* x = (const float*)d_in[0];
    const float* ea = (const float*)d_in[1];
    const int* ei = (const int*)d_in[2];
    const int* src = ei;
    const int* dst = ei + N_EDGES;
    const int* fb = (const int*)d_in[3];
    const int* gb = (const int*)d_in[4];

    const float* W1[3] = {(const float*)d_in[5], (const float*)d_in[11], (const float*)d_in[17]};
    const float* B1[3] = {(const float*)d_in[6], (const float*)d_in[12], (const float*)d_in[18]};
    const float* W2[3] = {(const float*)d_in[7], (const float*)d_in[13], (const float*)d_in[19]};
    const float* B2[3] = {(const float*)d_in[8], (const float*)d_in[14], (const float*)d_in[20]};
    const float* GG[3] = {(const float*)d_in[9], (const float*)d_in[15], (const float*)d_in[21]};
    const float* BB[3] = {(const float*)d_in[10], (const float*)d_in[16], (const float*)d_in[22]};

    float* out = (float*)d_out;
    const int T = 256;

    // ---- setup: CSR, edge aggregate, segment bounds, weight planes ----
    csr_zero<<<(N_NODES + T - 1) / T, T>>>();
    csr_hist<<<(N_EDGES + T - 1) / T, T>>>(dst);
    scan_local<<<(N_NODES + 255) / 256, 256>>>();
    scan_btot<<<1, 256>>>();
    scan_add<<<(N_NODES + T) / T, T>>>();
    csr_fill<<<(N_EDGES + T - 1) / T, T>>>(src, dst);
    agge_split<<<N_NODES, D_E>>>(ea);
    seg_bounds<<<(N_NODES + T - 1) / T, T>>>(fb, gb);
    for (int l = 0; l < 3; l++) {
        int fin = ((l == 0) ? DIM_IN : D_H) + D_E;
        int w1h = OFF_W + l * WSTRIDE, w1l = w1h + W1SZ;
        int w2h = w1l + W1SZ, w2l = w2h + W2SZ;
        convert_w<<<(256 * fin + T - 1) / T, T>>>(W1[l], fin, w1h, w1l);
        convert_w<<<(256 * 256 + T - 1) / T, T>>>(W2[l], 256, w2h, w2l);
    }

    int xin_off = -1;
    int xout_off = OFF_XA;     // l0->XA, l1->XB, l2->XA
    dim3 ggrid((N_NODES + 127) / 128, 2);

    for (int l = 0; l < 3; l++) {
        int din = (l == 0) ? DIM_IN : D_H;
        int fin = din + D_E;
        int w1h = OFF_W + l * WSTRIDE, w1l = w1h + W1SZ;
        int w2h = w1l + W1SZ, w2l = w2h + W2SZ;

        gather_split<<<N_NODES, fin>>>(x, xin_off, din);
        mma_gemm<<<ggrid, 256>>>(OFF_AGGH, OFF_AGGL, w1h, w1l, B1[l],
                                 N_NODES, fin, 1, OFF_H1H, OFF_H1L);
        mma_gemm<<<ggrid, 256>>>(OFF_H1H, OFF_H1L, w2h, w2l, B2[l],
                                 N_NODES, 256, 0, OFF_H, 0);
        zero_stats_kernel<<<1, 512>>>();
        colstats_kernel<<<256, 256>>>();
        bn_norm_kernel<<<(N_NODES * 256 + T - 1) / T, T>>>(GG[l], BB[l], xout_off);

        xin_off = xout_off;
        xout_off = (xout_off == OFF_XA) ? OFF_XB : OFF_XA;
    }

    pool_seg<<<N_FRAG, 256>>>(0, out);
    pool_seg<<<N_GRAPH, 256>>>(1, out + (size_t)N_FRAG * 256);
}